// round 8
// baseline (speedup 1.0000x reference)
#include <cuda_runtime.h>
#include <cuda_bf16.h>
#include <math.h>

// Problem constants (fixed by setup_inputs)
#define BS    16
#define T     1024
#define DF    80          // feature dim
#define DF4   20          // as float4
#define SIZE  4096
#define TPB   128         // 4 lanes per row -> 32 rows per block
#define RPB   32          // rows per block
#define TPAD  8           // +inf padding: prefetch stage may read c_sh[whi+7]
#define FULLM 0xFFFFFFFFu

// Device scratch (allocation-free): sorted centers + permutation per batch
__device__ float g_cs[BS * T];
__device__ int   g_ci[BS * T];

// ---------------------------------------------------------------------------
// Kernel 1: fp32 cumsum replicating jax.lax.associative_scan's association
// tree, then centers, then bitonic sort by c (monotone for every batch,
// incl. batch 0 whose cumsum row is zeroed by the reference).
// ---------------------------------------------------------------------------
__global__ void prep_kernel(const float* __restrict__ d) {
    __shared__ float r[2047];
    __shared__ float s[2047];
    __shared__ float cv[T];
    __shared__ int   ci[T];
    const int b = blockIdx.x;
    const int t = threadIdx.x;

    const float v = d[b * T + t];
    r[t] = v;
    __syncthreads();

    {   // upsweep: pair sums
        int off = 0, n = T;
        while (n > 1) {
            int noff = off + n;
            if (t < (n >> 1))
                r[noff + t] = __fadd_rn(r[off + 2 * t], r[off + 2 * t + 1]);
            __syncthreads();
            off = noff; n >>= 1;
        }
    }
    if (t == 0) s[2046] = r[2046];
    __syncthreads();
    #pragma unroll
    for (int L = 9; L >= 0; --L) {   // downsweep
        const int n    = T >> L;
        const int off  = 2048 - (2048 >> L);
        const int offn = 2048 - (2048 >> (L + 1));
        if (t < n) {
            float val;
            if (t == 0)        val = r[off];
            else if (t & 1)    val = s[offn + (t >> 1)];
            else               val = __fadd_rn(s[offn + (t >> 1) - 1], r[off + t]);
            s[off + t] = val;
        }
        __syncthreads();
    }

    float cs;
    if (b == 0)       cs = 0.0f;         // reference zeroes whole batch-0 row
    else if (t == 0)  cs = s[T - 1];     // rolled: total sum
    else              cs = s[t - 1];     // exclusive prefix
    cv[t] = __fadd_rn(0.5f * v, cs);
    ci[t] = t;
    __syncthreads();

    for (int k = 2; k <= T; k <<= 1) {   // bitonic sort ascending by cv
        for (int j = k >> 1; j > 0; j >>= 1) {
            int i = t ^ j;
            if (i > t) {
                bool up = ((t & k) == 0);
                float a = cv[t], bb = cv[i];
                if ((a > bb) == up) {
                    cv[t] = bb; cv[i] = a;
                    int tmp = ci[t]; ci[t] = ci[i]; ci[i] = tmp;
                }
            }
            __syncthreads();
        }
    }
    g_cs[b * T + t] = cv[t];
    g_ci[b * T + t] = ci[t];
}

// ---------------------------------------------------------------------------
// Main body: quad per row, 8 rows per warp, warp-union window, SOFTWARE
// PIPELINED — next chunk's weights/shuffles/pointers computed while current
// chunk's 20 LDG + 80 FFMA issue. Quantization-faithful scoring:
//   dt = fsub(t,c); sq = fmul(dt,dt); sc = -fdiv(sq,2s^2); e = fsub(sc,max)
// POW2: 2*sigma^2 is a power of two -> fmul by exact reciprocal == fdiv.
// ---------------------------------------------------------------------------
template<bool POW2>
__device__ __forceinline__ void run_rows(
    const float* __restrict__ c_sh, const int* __restrict__ i_sh,
    const float4* __restrict__ h4, float* __restrict__ out,
    int b, int s, int f, float two_s2, float inv2s2)
{
    const float tval = (float)s + 1.5f;

    auto lower = [&](float x) -> int {   // first k with c_sh[k] > x (sorted)
        int lo = 0, hi = T;
        while (lo < hi) {
            int m = (lo + hi) >> 1;
            if (c_sh[m] > x) hi = m; else lo = m + 1;
        }
        return lo;
    };

    // exact global max score (reference-rounded squares)
    int kc = lower(tval);
    int kA = kc < (T - 1) ? kc : (T - 1);
    int kB = (kc - 1) > 0 ? (kc - 1) : 0;
    float dA  = __fsub_rn(tval, c_sh[kA]);
    float dB  = __fsub_rn(tval, c_sh[kB]);
    float sqA = __fmul_rn(dA, dA);
    float sqB = __fmul_rn(dB, dB);
    float sqmin = fminf(sqA, sqB);
    const float score_max = POW2 ? -__fmul_rn(sqmin, inv2s2)
                                 : -__fdiv_rn(sqmin, two_s2);

    // window: e > -24
    const float rr  = sqrtf(sqmin + 24.0f * two_s2);
    int klo = lower(tval - rr);
    int khi = lower(tval + rr) - 1;

    // union over the warp's 8 consecutive rows (keeps lanes convergent)
    const int wlo = __reduce_min_sync(FULLM, klo);
    const int whi = __reduce_max_sync(FULLM, khi);

    const float4* __restrict__ hb = h4 + (size_t)b * T * DF4 + f;

    // stage: weights (faithful), quad-shuffle, and load pointers for chunk k0
    float w0, w1, w2, w3;
    const float4 *p0, *p1, *p2, *p3;
    auto stage = [&](int k0, float& a0, float& a1, float& a2, float& a3,
                     const float4*& q0, const float4*& q1,
                     const float4*& q2, const float4*& q3) {
        float dt = __fsub_rn(tval, c_sh[k0 + f]);
        float sq = __fmul_rn(dt, dt);
        float sc = POW2 ? -__fmul_rn(sq, inv2s2) : -__fdiv_rn(sq, two_s2);
        float e  = __fsub_rn(sc, score_max);
        a0 = __expf(e);                        // k = k0 + f
        a1 = __shfl_xor_sync(FULLM, a0, 1);    // k = k0 + (f^1)
        a2 = __shfl_xor_sync(FULLM, a0, 2);    // k = k0 + (f^2)
        a3 = __shfl_xor_sync(FULLM, a1, 2);    // k = k0 + (f^3)
        q0 = hb + (size_t)i_sh[k0 + f]       * DF4;
        q1 = hb + (size_t)i_sh[k0 + (f ^ 1)] * DF4;
        q2 = hb + (size_t)i_sh[k0 + (f ^ 2)] * DF4;
        q3 = hb + (size_t)i_sh[k0 + (f ^ 3)] * DF4;
    };

    float  l = 0.0f;
    float4 acc[5];
    #pragma unroll
    for (int j = 0; j < 5; ++j) acc[j] = make_float4(0.f, 0.f, 0.f, 0.f);

    stage(wlo, w0, w1, w2, w3, p0, p1, p2, p3);
    for (int k0 = wlo; k0 <= whi; k0 += 4) {
        // prefetch next chunk (c_sh/i_sh padded: reads at most whi+7 < T+8)
        float nw0, nw1, nw2, nw3;
        const float4 *q0, *q1, *q2, *q3;
        stage(k0 + 4, nw0, nw1, nw2, nw3, q0, q1, q2, q3);

        l += ((w0 + w1) + (w2 + w3));
        #pragma unroll
        for (int j = 0; j < 5; ++j) {
            float4 v0 = p0[4 * j];
            acc[j].x += w0 * v0.x; acc[j].y += w0 * v0.y;
            acc[j].z += w0 * v0.z; acc[j].w += w0 * v0.w;
            float4 v1 = p1[4 * j];
            acc[j].x += w1 * v1.x; acc[j].y += w1 * v1.y;
            acc[j].z += w1 * v1.z; acc[j].w += w1 * v1.w;
            float4 v2 = p2[4 * j];
            acc[j].x += w2 * v2.x; acc[j].y += w2 * v2.y;
            acc[j].z += w2 * v2.z; acc[j].w += w2 * v2.w;
            float4 v3 = p3[4 * j];
            acc[j].x += w3 * v3.x; acc[j].y += w3 * v3.y;
            acc[j].z += w3 * v3.z; acc[j].w += w3 * v3.w;
        }

        w0 = nw0; w1 = nw1; w2 = nw2; w3 = nw3;
        p0 = q0;  p1 = q1;  p2 = q2;  p3 = q3;
    }

    const float linv = 1.0f / l;
    float4* o = (float4*)out + ((size_t)b * SIZE + s) * DF4 + f;
    #pragma unroll
    for (int j = 0; j < 5; ++j) {
        float4 v;
        v.x = acc[j].x * linv; v.y = acc[j].y * linv;
        v.z = acc[j].z * linv; v.w = acc[j].w * linv;
        o[4 * j] = v;
    }
}

// ---------------------------------------------------------------------------
// Kernel 2: contiguous mapping (R5-style, beat interleaved in R7).
// ---------------------------------------------------------------------------
__global__ void __launch_bounds__(TPB) alignment_kernel(
    const float* __restrict__ h,      // [BS, T, DF]
    const float* __restrict__ sigma,  // [1]
    float* __restrict__ out)          // [BS, SIZE, DF]
{
    __shared__ float c_sh[T + TPAD];
    __shared__ int   i_sh[T + TPAD];
    const int b   = blockIdx.y;
    const int tid = threadIdx.x;
    const int f   = tid & 3;                  // lane-in-quad = feature group
    const int row = tid >> 2;                 // row-in-block (0..31)
    const int s   = blockIdx.x * RPB + row;

    for (int i = tid; i < T; i += TPB) {
        c_sh[i] = g_cs[b * T + i];
        i_sh[i] = g_ci[b * T + i];
    }
    if (tid < TPAD) { c_sh[T + tid] = INFINITY; i_sh[T + tid] = 0; }
    __syncthreads();

    const float sg     = sigma[0];
    const float two_s2 = 2.0f * sg * sg;
    const unsigned tb  = __float_as_uint(two_s2);
    const bool pow2    = ((tb & 0x007FFFFFu) == 0u) && (two_s2 > 0.0f);
    const float inv2s2 = 1.0f / two_s2;       // exact when pow2

    const float4* h4 = (const float4*)h;
    if (pow2) run_rows<true >(c_sh, i_sh, h4, out, b, s, f, two_s2, inv2s2);
    else      run_rows<false>(c_sh, i_sh, h4, out, b, s, f, two_s2, inv2s2);
}

// ---------------------------------------------------------------------------
extern "C" void kernel_launch(void* const* d_in, const int* in_sizes, int n_in,
                              void* d_out, int out_size) {
    const float* h     = (const float*)d_in[0];  // [16,1024,80]
    const float* d     = (const float*)d_in[1];  // [16,1024]
    const float* sigma = (const float*)d_in[2];  // [1]

    prep_kernel<<<BS, T>>>(d);
    dim3 grid(SIZE / RPB, BS);                   // 128 x 16
    alignment_kernel<<<grid, TPB>>>(h, sigma, (float*)d_out);
}

// round 9
// speedup vs baseline: 1.0072x; 1.0072x over previous
#include <cuda_runtime.h>
#include <cuda_bf16.h>
#include <math.h>

// Problem constants (fixed by setup_inputs)
#define BS    16
#define T     1024
#define DF    80          // feature dim
#define DF4   20          // as float4
#define SIZE  4096
#define TPB   256         // 8 warps; quad per row -> 64 rows per block
#define RPB   64
#define TILEK 64          // k-tile per weight phase
#define TPAD  (TILEK + 4) // +inf padding: tile/chunk may read past whi
#define FULLM 0xFFFFFFFFu

// Device scratch (allocation-free): sorted centers + permutation per batch
__device__ float g_cs[BS * T];
__device__ int   g_ci[BS * T];

// ---------------------------------------------------------------------------
// Kernel 1: fp32 cumsum replicating jax.lax.associative_scan's association
// tree, then centers, then bitonic sort by c (monotone for every batch,
// incl. batch 0 whose cumsum row is zeroed by the reference).
// ---------------------------------------------------------------------------
__global__ void prep_kernel(const float* __restrict__ d) {
    __shared__ float r[2047];
    __shared__ float s[2047];
    __shared__ float cv[T];
    __shared__ int   ci[T];
    const int b = blockIdx.x;
    const int t = threadIdx.x;

    const float v = d[b * T + t];
    r[t] = v;
    __syncthreads();

    {   // upsweep: pair sums
        int off = 0, n = T;
        while (n > 1) {
            int noff = off + n;
            if (t < (n >> 1))
                r[noff + t] = __fadd_rn(r[off + 2 * t], r[off + 2 * t + 1]);
            __syncthreads();
            off = noff; n >>= 1;
        }
    }
    if (t == 0) s[2046] = r[2046];
    __syncthreads();
    #pragma unroll
    for (int L = 9; L >= 0; --L) {   // downsweep
        const int n    = T >> L;
        const int off  = 2048 - (2048 >> L);
        const int offn = 2048 - (2048 >> (L + 1));
        if (t < n) {
            float val;
            if (t == 0)        val = r[off];
            else if (t & 1)    val = s[offn + (t >> 1)];
            else               val = __fadd_rn(s[offn + (t >> 1) - 1], r[off + t]);
            s[off + t] = val;
        }
        __syncthreads();
    }

    float cs;
    if (b == 0)       cs = 0.0f;         // reference zeroes whole batch-0 row
    else if (t == 0)  cs = s[T - 1];     // rolled: total sum
    else              cs = s[t - 1];     // exclusive prefix
    cv[t] = __fadd_rn(0.5f * v, cs);
    ci[t] = t;
    __syncthreads();

    for (int k = 2; k <= T; k <<= 1) {   // bitonic sort ascending by cv
        for (int j = k >> 1; j > 0; j >>= 1) {
            int i = t ^ j;
            if (i > t) {
                bool up = ((t & k) == 0);
                float a = cv[t], bb = cv[i];
                if ((a > bb) == up) {
                    cv[t] = bb; cv[i] = a;
                    int tmp = ci[t]; ci[t] = ci[i]; ci[i] = tmp;
                }
            }
            __syncthreads();
        }
    }
    g_cs[b * T + t] = cv[t];
    g_ci[b * T + t] = ci[t];
}

// ---------------------------------------------------------------------------
// Main body: quad per row, 8 rows per warp. Per 64-k tile, a fully parallel
// WEIGHT PHASE computes all 8x64 quantization-faithful weights into shared
// memory (each lane: 16 independent exps), then the accumulate loop is pure
// LDS + LDG + FFMA with no MUFU/SHFL dependencies.
//   dt = fsub(t,c); sq = fmul(dt,dt); sc = -fdiv(sq,2s^2); e = fsub(sc,max)
// POW2: 2*sigma^2 is a power of two -> fmul by exact reciprocal == fdiv.
// c padded with +inf  =>  padded k's yield w = exp(-inf) = 0 exactly; real
// k's past the window bound are genuine softmax terms (included correctly).
// ---------------------------------------------------------------------------
template<bool POW2>
__device__ __forceinline__ void run_rows(
    const float* __restrict__ c_sh, const int* __restrict__ i_sh,
    float* __restrict__ wrow,              // this warp's 64x8 weight tile
    const float4* __restrict__ h4, float* __restrict__ out,
    int b, int s_warp0, int lane, float two_s2, float inv2s2)
{
    const int f    = lane & 3;             // lane-in-quad = feature group
    const int quad = lane >> 2;            // row-in-warp (0..7)
    const int s    = s_warp0 + quad;
    const float tval = (float)s + 1.5f;

    auto lower = [&](float x) -> int {     // first k with c_sh[k] > x (sorted)
        int lo = 0, hi = T;
        while (lo < hi) {
            int m = (lo + hi) >> 1;
            if (c_sh[m] > x) hi = m; else lo = m + 1;
        }
        return lo;
    };

    // exact global max score (reference-rounded squares)
    int kc = lower(tval);
    int kA = kc < (T - 1) ? kc : (T - 1);
    int kB = (kc - 1) > 0 ? (kc - 1) : 0;
    float dA  = __fsub_rn(tval, c_sh[kA]);
    float dB  = __fsub_rn(tval, c_sh[kB]);
    float sqA = __fmul_rn(dA, dA);
    float sqB = __fmul_rn(dB, dB);
    float sqmin = fminf(sqA, sqB);
    const float score_max = POW2 ? -__fmul_rn(sqmin, inv2s2)
                                 : -__fdiv_rn(sqmin, two_s2);

    // window: e > -24
    const float rr  = sqrtf(sqmin + 24.0f * two_s2);
    int klo = lower(tval - rr);
    int khi = lower(tval + rr) - 1;

    // union over the warp's 8 consecutive rows
    const int wlo = __reduce_min_sync(FULLM, klo);
    const int whi = __reduce_max_sync(FULLM, khi);

    // weight-phase lane role: row r_ph = lane&7, k-substride kb = lane>>3
    const int   r_ph    = lane & 7;
    const int   kb      = lane >> 3;                 // 0..3
    const float smax_ph = __shfl_sync(FULLM, score_max, r_ph * 4);
    const float tval_ph = (float)(s_warp0 + r_ph) + 1.5f;

    const float4* __restrict__ hb = h4 + (size_t)b * T * DF4 + f;

    float  l = 0.0f;
    float4 acc[5];
    #pragma unroll
    for (int j = 0; j < 5; ++j) acc[j] = make_float4(0.f, 0.f, 0.f, 0.f);

    for (int k0t = wlo; k0t <= whi; k0t += TILEK) {
        // ---- phase 1: 8 rows x TILEK weights, 16 independent exps per lane.
        // STS addr word = kkl*8 + r_ph = lane + 32*i  -> conflict-free.
        #pragma unroll 4
        for (int i = 0; i < TILEK / 4; ++i) {
            int   kkl = kb + 4 * i;
            float cc  = c_sh[k0t + kkl];             // 4 distinct -> broadcast
            float dt  = __fsub_rn(tval_ph, cc);
            float sq  = __fmul_rn(dt, dt);
            float sc  = POW2 ? -__fmul_rn(sq, inv2s2) : -__fdiv_rn(sq, two_s2);
            float e   = __fsub_rn(sc, smax_ph);
            wrow[kkl * 8 + r_ph] = __expf(e);        // 0 for padded k
        }
        __syncwarp();

        // ---- phase 2: accumulate. w reads: 8 consecutive words, broadcast
        // to the 4 lanes of each quad; idx reads warp-uniform.
        const int kend = whi < (k0t + TILEK - 1) ? whi : (k0t + TILEK - 1);
        for (int k0 = k0t; k0 <= kend; k0 += 4) {
            const int kl = (k0 - k0t) * 8 + quad;
            float w0 = wrow[kl];
            float w1 = wrow[kl + 8];
            float w2 = wrow[kl + 16];
            float w3 = wrow[kl + 24];
            const float4* p0 = hb + (size_t)i_sh[k0]     * DF4;
            const float4* p1 = hb + (size_t)i_sh[k0 + 1] * DF4;
            const float4* p2 = hb + (size_t)i_sh[k0 + 2] * DF4;
            const float4* p3 = hb + (size_t)i_sh[k0 + 3] * DF4;

            l += ((w0 + w1) + (w2 + w3));
            #pragma unroll
            for (int j = 0; j < 5; ++j) {
                float4 v0 = p0[4 * j];
                acc[j].x += w0 * v0.x; acc[j].y += w0 * v0.y;
                acc[j].z += w0 * v0.z; acc[j].w += w0 * v0.w;
                float4 v1 = p1[4 * j];
                acc[j].x += w1 * v1.x; acc[j].y += w1 * v1.y;
                acc[j].z += w1 * v1.z; acc[j].w += w1 * v1.w;
                float4 v2 = p2[4 * j];
                acc[j].x += w2 * v2.x; acc[j].y += w2 * v2.y;
                acc[j].z += w2 * v2.z; acc[j].w += w2 * v2.w;
                float4 v3 = p3[4 * j];
                acc[j].x += w3 * v3.x; acc[j].y += w3 * v3.y;
                acc[j].z += w3 * v3.z; acc[j].w += w3 * v3.w;
            }
        }
        __syncwarp();
    }

    const float linv = 1.0f / l;
    float4* o = (float4*)out + ((size_t)b * SIZE + s) * DF4 + f;
    #pragma unroll
    for (int j = 0; j < 5; ++j) {
        float4 v;
        v.x = acc[j].x * linv; v.y = acc[j].y * linv;
        v.z = acc[j].z * linv; v.w = acc[j].w * linv;
        o[4 * j] = v;
    }
}

// ---------------------------------------------------------------------------
// Kernel 2: contiguous row mapping (best in R5/R7 comparison).
// ---------------------------------------------------------------------------
__global__ void __launch_bounds__(TPB, 4) alignment_kernel(
    const float* __restrict__ h,      // [BS, T, DF]
    const float* __restrict__ sigma,  // [1]
    float* __restrict__ out)          // [BS, SIZE, DF]
{
    __shared__ float c_sh[T + TPAD];
    __shared__ int   i_sh[T + TPAD];
    __shared__ float w_sm[8][TILEK * 8];       // per-warp weight tiles (16KB)
    const int b    = blockIdx.y;
    const int tid  = threadIdx.x;
    const int lane = tid & 31;
    const int wid  = tid >> 5;

    for (int i = tid; i < T; i += TPB) {
        c_sh[i] = g_cs[b * T + i];
        i_sh[i] = g_ci[b * T + i];
    }
    for (int i = tid; i < TPAD; i += TPB) {
        c_sh[T + i] = INFINITY;                // exp(-inf) = 0 padding
        i_sh[T + i] = 0;
    }
    __syncthreads();

    const float sg     = sigma[0];
    const float two_s2 = 2.0f * sg * sg;
    const unsigned tb  = __float_as_uint(two_s2);
    const bool pow2    = ((tb & 0x007FFFFFu) == 0u) && (two_s2 > 0.0f);
    const float inv2s2 = 1.0f / two_s2;        // exact when pow2

    const int s_warp0 = blockIdx.x * RPB + wid * 8;
    const float4* h4  = (const float4*)h;

    if (pow2) run_rows<true >(c_sh, i_sh, w_sm[wid], h4, out, b, s_warp0,
                              lane, two_s2, inv2s2);
    else      run_rows<false>(c_sh, i_sh, w_sm[wid], h4, out, b, s_warp0,
                              lane, two_s2, inv2s2);
}

// ---------------------------------------------------------------------------
extern "C" void kernel_launch(void* const* d_in, const int* in_sizes, int n_in,
                              void* d_out, int out_size) {
    const float* h     = (const float*)d_in[0];  // [16,1024,80]
    const float* d     = (const float*)d_in[1];  // [16,1024]
    const float* sigma = (const float*)d_in[2];  // [1]

    prep_kernel<<<BS, T>>>(d);
    dim3 grid(SIZE / RPB, BS);                   // 64 x 16
    alignment_kernel<<<grid, TPB>>>(h, sigma, (float*)d_out);
}

// round 10
// speedup vs baseline: 1.1586x; 1.1503x over previous
#include <cuda_runtime.h>
#include <cuda_bf16.h>
#include <math.h>

// Problem constants (fixed by setup_inputs)
#define BS    16
#define T     1024
#define DF    80          // feature dim
#define DF4   20          // as float4
#define SIZE  4096
#define TPB   256         // quad per row -> 64 rows per block
#define RPB   64
#define TPAD  8           // padded length: chunk loop may read c_sh[whi+3]
#define PT    (T + TPAD)  // padded row count of h_perm
#define FULLM 0xFFFFFFFFu

// Device scratch (allocation-free)
__device__ float g_cs[BS * T];          // sorted centers
__device__ int   g_ci[BS * T];          // permutation
__device__ float g_hp[BS * PT * DF];    // h rows permuted by sorted order

// ---------------------------------------------------------------------------
// Kernel 1: fp32 cumsum replicating jax.lax.associative_scan's association
// tree, then centers, then bitonic sort by c (monotone for every batch,
// incl. batch 0 whose cumsum row is zeroed by the reference).
// ---------------------------------------------------------------------------
__global__ void prep_kernel(const float* __restrict__ d) {
    __shared__ float r[2047];
    __shared__ float s[2047];
    __shared__ float cv[T];
    __shared__ int   ci[T];
    const int b = blockIdx.x;
    const int t = threadIdx.x;

    const float v = d[b * T + t];
    r[t] = v;
    __syncthreads();

    {   // upsweep: pair sums
        int off = 0, n = T;
        while (n > 1) {
            int noff = off + n;
            if (t < (n >> 1))
                r[noff + t] = __fadd_rn(r[off + 2 * t], r[off + 2 * t + 1]);
            __syncthreads();
            off = noff; n >>= 1;
        }
    }
    if (t == 0) s[2046] = r[2046];
    __syncthreads();
    #pragma unroll
    for (int L = 9; L >= 0; --L) {   // downsweep
        const int n    = T >> L;
        const int off  = 2048 - (2048 >> L);
        const int offn = 2048 - (2048 >> (L + 1));
        if (t < n) {
            float val;
            if (t == 0)        val = r[off];
            else if (t & 1)    val = s[offn + (t >> 1)];
            else               val = __fadd_rn(s[offn + (t >> 1) - 1], r[off + t]);
            s[off + t] = val;
        }
        __syncthreads();
    }

    float cs;
    if (b == 0)       cs = 0.0f;         // reference zeroes whole batch-0 row
    else if (t == 0)  cs = s[T - 1];     // rolled: total sum
    else              cs = s[t - 1];     // exclusive prefix
    cv[t] = __fadd_rn(0.5f * v, cs);
    ci[t] = t;
    __syncthreads();

    for (int k = 2; k <= T; k <<= 1) {   // bitonic sort ascending by cv
        for (int j = k >> 1; j > 0; j >>= 1) {
            int i = t ^ j;
            if (i > t) {
                bool up = ((t & k) == 0);
                float a = cv[t], bb = cv[i];
                if ((a > bb) == up) {
                    cv[t] = bb; cv[i] = a;
                    int tmp = ci[t]; ci[t] = ci[i]; ci[i] = tmp;
                }
            }
            __syncthreads();
        }
    }
    g_cs[b * T + t] = cv[t];
    g_ci[b * T + t] = ci[t];
}

// ---------------------------------------------------------------------------
// Kernel 1b: materialize the permutation — h_perm[b][k][:] = h[b][ci[b][k]][:]
// Pad rows k in [T, PT) are zeroed (their weights are exactly 0). The random
// gather happens ONCE here (coalesced writes) instead of in the hot loop.
// ---------------------------------------------------------------------------
__global__ void perm_kernel(const float* __restrict__ h) {
    const int e = blockIdx.x * blockDim.x + threadIdx.x;   // element id
    const int c = e % DF;
    const int k = (e / DF) % PT;
    const int b = e / (DF * PT);
    if (b >= BS) return;
    float v = 0.0f;
    if (k < T) {
        int src = g_ci[b * T + k];
        v = h[((size_t)b * T + src) * DF + c];
    }
    g_hp[((size_t)b * PT + k) * DF + c] = v;
}

// ---------------------------------------------------------------------------
// Main body (R5 structure + pow2): quad per row, 8 rows per warp, warp-union
// window, quantization-faithful scoring:
//   dt = fsub(t,c); sq = fmul(dt,dt); sc = -fdiv(sq,2s^2); e = fsub(sc,max)
// POW2: 2*sigma^2 power of two -> fmul by exact reciprocal == fdiv (bitwise).
// h_perm is CONTIGUOUS in k: the inner loop streams sequential memory.
// ---------------------------------------------------------------------------
template<bool POW2>
__device__ __forceinline__ void run_rows(
    const float* __restrict__ c_sh,
    float* __restrict__ out,
    int b, int s, int f, float two_s2, float inv2s2)
{
    const float tval = (float)s + 1.5f;

    auto lower = [&](float x) -> int {   // first k with c_sh[k] > x (sorted)
        int lo = 0, hi = T;
        while (lo < hi) {
            int m = (lo + hi) >> 1;
            if (c_sh[m] > x) hi = m; else lo = m + 1;
        }
        return lo;
    };

    // exact global max score (reference-rounded squares)
    int kc = lower(tval);
    int kA = kc < (T - 1) ? kc : (T - 1);
    int kB = (kc - 1) > 0 ? (kc - 1) : 0;
    float dA  = __fsub_rn(tval, c_sh[kA]);
    float dB  = __fsub_rn(tval, c_sh[kB]);
    float sqA = __fmul_rn(dA, dA);
    float sqB = __fmul_rn(dB, dB);
    float sqmin = fminf(sqA, sqB);
    const float score_max = POW2 ? -__fmul_rn(sqmin, inv2s2)
                                 : -__fdiv_rn(sqmin, two_s2);

    // window: e > -24
    const float rr  = sqrtf(sqmin + 24.0f * two_s2);
    int klo = lower(tval - rr);
    int khi = lower(tval + rr) - 1;

    // union over the warp's 8 consecutive rows (keeps lanes convergent)
    const int wlo = __reduce_min_sync(FULLM, klo);
    const int whi = __reduce_max_sync(FULLM, khi);

    const float4* __restrict__ hb =
        (const float4*)g_hp + (size_t)b * PT * DF4 + f;

    float  l = 0.0f;
    float4 acc[5];
    #pragma unroll
    for (int j = 0; j < 5; ++j) acc[j] = make_float4(0.f, 0.f, 0.f, 0.f);

    // chunk of 4 k's: lane f computes the faithful weight for k0+f, quad-
    // shuffles, then accumulates 5 float4 columns from 4 CONSECUTIVE h rows.
    for (int k0 = wlo; k0 <= whi; k0 += 4) {
        float dt = __fsub_rn(tval, c_sh[k0 + f]);
        float sq = __fmul_rn(dt, dt);
        float sc = POW2 ? -__fmul_rn(sq, inv2s2) : -__fdiv_rn(sq, two_s2);
        float e  = __fsub_rn(sc, score_max);
        float w0 = __expf(e);                           // k = k0 + f
        float w1 = __shfl_xor_sync(FULLM, w0, 1);       // k = k0 + (f^1)
        float w2 = __shfl_xor_sync(FULLM, w0, 2);       // k = k0 + (f^2)
        float w3 = __shfl_xor_sync(FULLM, w1, 2);       // k = k0 + (f^3)

        l += ((w0 + w1) + (w2 + w3));

        const float4* p0 = hb + (size_t)(k0 + f)       * DF4;
        const float4* p1 = hb + (size_t)(k0 + (f ^ 1)) * DF4;
        const float4* p2 = hb + (size_t)(k0 + (f ^ 2)) * DF4;
        const float4* p3 = hb + (size_t)(k0 + (f ^ 3)) * DF4;
        #pragma unroll
        for (int j = 0; j < 5; ++j) {
            float4 v0 = p0[4 * j];
            acc[j].x += w0 * v0.x; acc[j].y += w0 * v0.y;
            acc[j].z += w0 * v0.z; acc[j].w += w0 * v0.w;
            float4 v1 = p1[4 * j];
            acc[j].x += w1 * v1.x; acc[j].y += w1 * v1.y;
            acc[j].z += w1 * v1.z; acc[j].w += w1 * v1.w;
            float4 v2 = p2[4 * j];
            acc[j].x += w2 * v2.x; acc[j].y += w2 * v2.y;
            acc[j].z += w2 * v2.z; acc[j].w += w2 * v2.w;
            float4 v3 = p3[4 * j];
            acc[j].x += w3 * v3.x; acc[j].y += w3 * v3.y;
            acc[j].z += w3 * v3.z; acc[j].w += w3 * v3.w;
        }
    }

    const float linv = 1.0f / l;
    float4* o = (float4*)out + ((size_t)b * SIZE + s) * DF4 + f;
    #pragma unroll
    for (int j = 0; j < 5; ++j) {
        float4 v;
        v.x = acc[j].x * linv; v.y = acc[j].y * linv;
        v.z = acc[j].z * linv; v.w = acc[j].w * linv;
        o[4 * j] = v;
    }
}

// ---------------------------------------------------------------------------
// Kernel 2: contiguous row mapping (best known from R5/R7 comparison).
// ---------------------------------------------------------------------------
__global__ void __launch_bounds__(TPB) alignment_kernel(
    const float* __restrict__ sigma,  // [1]
    float* __restrict__ out)          // [BS, SIZE, DF]
{
    __shared__ float c_sh[PT];
    const int b   = blockIdx.y;
    const int tid = threadIdx.x;
    const int f   = tid & 3;                 // lane-in-quad = feature group
    const int row = tid >> 2;                // row-in-block (0..63)
    const int s   = blockIdx.x * RPB + row;

    for (int i = tid; i < T; i += TPB)
        c_sh[i] = g_cs[b * T + i];
    if (tid < TPAD) c_sh[T + tid] = INFINITY;    // exp(-inf) = 0 padding
    __syncthreads();

    const float sg     = sigma[0];
    const float two_s2 = 2.0f * sg * sg;
    const unsigned tb  = __float_as_uint(two_s2);
    const bool pow2    = ((tb & 0x007FFFFFu) == 0u) && (two_s2 > 0.0f);
    const float inv2s2 = 1.0f / two_s2;          // exact when pow2

    if (pow2) run_rows<true >(c_sh, out, b, s, f, two_s2, inv2s2);
    else      run_rows<false>(c_sh, out, b, s, f, two_s2, inv2s2);
}

// ---------------------------------------------------------------------------
extern "C" void kernel_launch(void* const* d_in, const int* in_sizes, int n_in,
                              void* d_out, int out_size) {
    const float* h     = (const float*)d_in[0];  // [16,1024,80]
    const float* d     = (const float*)d_in[1];  // [16,1024]
    const float* sigma = (const float*)d_in[2];  // [1]

    prep_kernel<<<BS, T>>>(d);
    const int pelems = BS * PT * DF;
    perm_kernel<<<(pelems + 255) / 256, 256>>>(h);
    dim3 grid(SIZE / RPB, BS);                   // 64 x 16
    alignment_kernel<<<grid, TPB>>>(sigma, (float*)d_out);
}

// round 11
// speedup vs baseline: 1.9945x; 1.7214x over previous
#include <cuda_runtime.h>
#include <cuda_bf16.h>
#include <math.h>

// Problem constants (fixed by setup_inputs)
#define BS    16
#define T     1024
#define DF    80          // feature dim
#define DF4   20          // as float4
#define SIZE  4096
#define TPB   256         // quad per row -> 64 rows per block
#define RPB   64
#define NZ    4           // split-K factor
#define TPAD  8           // padded length: chunk loop may read c_sh[*+3]
#define PT    (T + TPAD)  // padded row count of h_perm
#define NROW  (BS * SIZE)
#define FULLM 0xFFFFFFFFu

// Device scratch (allocation-free)
__device__ float g_cs[BS * T];             // sorted centers
__device__ int   g_ci[BS * T];             // permutation
__device__ float g_hp[BS * PT * DF];       // h rows permuted by sorted order
__device__ float g_part[NZ * NROW * DF];   // split-K partial numerators
__device__ float g_lpart[NZ * NROW];       // split-K partial denominators

// ---------------------------------------------------------------------------
// Kernel 1: fp32 cumsum replicating jax.lax.associative_scan's association
// tree, then centers, then bitonic sort by c (monotone for every batch,
// incl. batch 0 whose cumsum row is zeroed by the reference).
// ---------------------------------------------------------------------------
__global__ void prep_kernel(const float* __restrict__ d) {
    __shared__ float r[2047];
    __shared__ float s[2047];
    __shared__ float cv[T];
    __shared__ int   ci[T];
    const int b = blockIdx.x;
    const int t = threadIdx.x;

    const float v = d[b * T + t];
    r[t] = v;
    __syncthreads();

    {   // upsweep: pair sums
        int off = 0, n = T;
        while (n > 1) {
            int noff = off + n;
            if (t < (n >> 1))
                r[noff + t] = __fadd_rn(r[off + 2 * t], r[off + 2 * t + 1]);
            __syncthreads();
            off = noff; n >>= 1;
        }
    }
    if (t == 0) s[2046] = r[2046];
    __syncthreads();
    #pragma unroll
    for (int L = 9; L >= 0; --L) {   // downsweep
        const int n    = T >> L;
        const int off  = 2048 - (2048 >> L);
        const int offn = 2048 - (2048 >> (L + 1));
        if (t < n) {
            float val;
            if (t == 0)        val = r[off];
            else if (t & 1)    val = s[offn + (t >> 1)];
            else               val = __fadd_rn(s[offn + (t >> 1) - 1], r[off + t]);
            s[off + t] = val;
        }
        __syncthreads();
    }

    float cs;
    if (b == 0)       cs = 0.0f;         // reference zeroes whole batch-0 row
    else if (t == 0)  cs = s[T - 1];     // rolled: total sum
    else              cs = s[t - 1];     // exclusive prefix
    cv[t] = __fadd_rn(0.5f * v, cs);
    ci[t] = t;
    __syncthreads();

    for (int k = 2; k <= T; k <<= 1) {   // bitonic sort ascending by cv
        for (int j = k >> 1; j > 0; j >>= 1) {
            int i = t ^ j;
            if (i > t) {
                bool up = ((t & k) == 0);
                float a = cv[t], bb = cv[i];
                if ((a > bb) == up) {
                    cv[t] = bb; cv[i] = a;
                    int tmp = ci[t]; ci[t] = ci[i]; ci[i] = tmp;
                }
            }
            __syncthreads();
        }
    }
    g_cs[b * T + t] = cv[t];
    g_ci[b * T + t] = ci[t];
}

// ---------------------------------------------------------------------------
// Kernel 1b: h_perm[b][k][:] = h[b][ci[b][k]][:]; pad rows zeroed.
// ---------------------------------------------------------------------------
__global__ void perm_kernel(const float* __restrict__ h) {
    const int e = blockIdx.x * blockDim.x + threadIdx.x;
    const int c = e % DF;
    const int k = (e / DF) % PT;
    const int b = e / (DF * PT);
    if (b >= BS) return;
    float v = 0.0f;
    if (k < T) {
        int src = g_ci[b * T + k];
        v = h[((size_t)b * T + src) * DF + c];
    }
    g_hp[((size_t)b * PT + k) * DF + c] = v;
}

// ---------------------------------------------------------------------------
// Main body: quad per row, 8 rows per warp, warp-union window, SPLIT-K —
// block z handles the z-th quarter of the union window, writing partial
// numerator/denominator slabs. Quantization-faithful scoring as validated:
//   dt = fsub(t,c); sq = fmul(dt,dt); sc = -fdiv(sq,2s^2); e = fsub(sc,max)
// POW2: 2*sigma^2 power of two -> fmul by exact reciprocal == fdiv (bitwise).
// ---------------------------------------------------------------------------
template<bool POW2>
__device__ __forceinline__ void run_rows(
    const float* __restrict__ c_sh,
    int b, int s, int f, int z, float two_s2, float inv2s2)
{
    const float tval = (float)s + 1.5f;

    auto lower = [&](float x) -> int {   // first k with c_sh[k] > x (sorted)
        int lo = 0, hi = T;
        while (lo < hi) {
            int m = (lo + hi) >> 1;
            if (c_sh[m] > x) hi = m; else lo = m + 1;
        }
        return lo;
    };

    // exact global max score (reference-rounded squares)
    int kc = lower(tval);
    int kA = kc < (T - 1) ? kc : (T - 1);
    int kB = (kc - 1) > 0 ? (kc - 1) : 0;
    float dA  = __fsub_rn(tval, c_sh[kA]);
    float dB  = __fsub_rn(tval, c_sh[kB]);
    float sqA = __fmul_rn(dA, dA);
    float sqB = __fmul_rn(dB, dB);
    float sqmin = fminf(sqA, sqB);
    const float score_max = POW2 ? -__fmul_rn(sqmin, inv2s2)
                                 : -__fdiv_rn(sqmin, two_s2);

    // window: e > -24
    const float rr  = sqrtf(sqmin + 24.0f * two_s2);
    int klo = lower(tval - rr);
    int khi = lower(tval + rr) - 1;

    // union over the warp's 8 consecutive rows (keeps lanes convergent)
    const int wlo = __reduce_min_sync(FULLM, klo);
    const int whi = __reduce_max_sync(FULLM, khi);

    // z-th quarter of the union window
    const int len = whi - wlo + 1;
    const int zlo = wlo + (len * z) / NZ;
    const int zhi = wlo + (len * (z + 1)) / NZ - 1;

    const float4* __restrict__ hb =
        (const float4*)g_hp + (size_t)b * PT * DF4 + f;

    float  l = 0.0f;
    float4 acc[5];
    #pragma unroll
    for (int j = 0; j < 5; ++j) acc[j] = make_float4(0.f, 0.f, 0.f, 0.f);

    for (int k0 = zlo; k0 <= zhi; k0 += 4) {
        const int kk = k0 + f;
        float dt = __fsub_rn(tval, c_sh[kk]);
        float sq = __fmul_rn(dt, dt);
        float sc = POW2 ? -__fmul_rn(sq, inv2s2) : -__fdiv_rn(sq, two_s2);
        float e  = __fsub_rn(sc, score_max);
        float w0 = __expf(e);
        if (kk > zhi) w0 = 0.0f;                  // no double-count across z
        float w1 = __shfl_xor_sync(FULLM, w0, 1); // k = k0 + (f^1)
        float w2 = __shfl_xor_sync(FULLM, w0, 2); // k = k0 + (f^2)
        float w3 = __shfl_xor_sync(FULLM, w1, 2); // k = k0 + (f^3)

        l += ((w0 + w1) + (w2 + w3));

        const float4* p0 = hb + (size_t)(k0 + f)       * DF4;
        const float4* p1 = hb + (size_t)(k0 + (f ^ 1)) * DF4;
        const float4* p2 = hb + (size_t)(k0 + (f ^ 2)) * DF4;
        const float4* p3 = hb + (size_t)(k0 + (f ^ 3)) * DF4;
        #pragma unroll
        for (int j = 0; j < 5; ++j) {
            float4 v0 = p0[4 * j];
            acc[j].x += w0 * v0.x; acc[j].y += w0 * v0.y;
            acc[j].z += w0 * v0.z; acc[j].w += w0 * v0.w;
            float4 v1 = p1[4 * j];
            acc[j].x += w1 * v1.x; acc[j].y += w1 * v1.y;
            acc[j].z += w1 * v1.z; acc[j].w += w1 * v1.w;
            float4 v2 = p2[4 * j];
            acc[j].x += w2 * v2.x; acc[j].y += w2 * v2.y;
            acc[j].z += w2 * v2.z; acc[j].w += w2 * v2.w;
            float4 v3 = p3[4 * j];
            acc[j].x += w3 * v3.x; acc[j].y += w3 * v3.y;
            acc[j].z += w3 * v3.z; acc[j].w += w3 * v3.w;
        }
    }

    // write partial slabs (always, incl. zeros — slabs fully overwritten)
    const size_t rowid = (size_t)b * SIZE + s;
    float4* po = (float4*)g_part + ((size_t)z * NROW + rowid) * DF4 + f;
    #pragma unroll
    for (int j = 0; j < 5; ++j) po[4 * j] = acc[j];
    if (f == 0) g_lpart[(size_t)z * NROW + rowid] = l;
}

// ---------------------------------------------------------------------------
// Kernel 2: split-K main kernel, contiguous row mapping.
// ---------------------------------------------------------------------------
__global__ void __launch_bounds__(TPB) alignment_kernel(
    const float* __restrict__ sigma)   // [1]
{
    __shared__ float c_sh[PT];
    const int b   = blockIdx.y;
    const int z   = blockIdx.z;
    const int tid = threadIdx.x;
    const int f   = tid & 3;                 // lane-in-quad = feature group
    const int row = tid >> 2;                // row-in-block (0..63)
    const int s   = blockIdx.x * RPB + row;

    for (int i = tid; i < T; i += TPB)
        c_sh[i] = g_cs[b * T + i];
    if (tid < TPAD) c_sh[T + tid] = INFINITY;    // exp(-inf) = 0 padding
    __syncthreads();

    const float sg     = sigma[0];
    const float two_s2 = 2.0f * sg * sg;
    const unsigned tb  = __float_as_uint(two_s2);
    const bool pow2    = ((tb & 0x007FFFFFu) == 0u) && (two_s2 > 0.0f);
    const float inv2s2 = 1.0f / two_s2;          // exact when pow2

    if (pow2) run_rows<true >(c_sh, b, s, f, z, two_s2, inv2s2);
    else      run_rows<false>(c_sh, b, s, f, z, two_s2, inv2s2);
}

// ---------------------------------------------------------------------------
// Kernel 3: combine partials — out = (sum_z acc_z) / (sum_z l_z).
// ---------------------------------------------------------------------------
__global__ void combine_kernel(float* __restrict__ out) {
    const int e = blockIdx.x * blockDim.x + threadIdx.x;  // float4 id
    if (e >= NROW * DF4) return;
    const int rowid = e / DF4;

    float lsum = 0.0f;
    #pragma unroll
    for (int z = 0; z < NZ; ++z)
        lsum += g_lpart[(size_t)z * NROW + rowid];

    float4 v = make_float4(0.f, 0.f, 0.f, 0.f);
    #pragma unroll
    for (int z = 0; z < NZ; ++z) {
        float4 p = ((const float4*)g_part)[(size_t)z * NROW * DF4 + e];
        v.x += p.x; v.y += p.y; v.z += p.z; v.w += p.w;
    }
    const float linv = 1.0f / lsum;
    v.x *= linv; v.y *= linv; v.z *= linv; v.w *= linv;
    ((float4*)out)[e] = v;
}

// ---------------------------------------------------------------------------
extern "C" void kernel_launch(void* const* d_in, const int* in_sizes, int n_in,
                              void* d_out, int out_size) {
    const float* h     = (const float*)d_in[0];  // [16,1024,80]
    const float* d     = (const float*)d_in[1];  // [16,1024]
    const float* sigma = (const float*)d_in[2];  // [1]

    prep_kernel<<<BS, T>>>(d);
    const int pelems = BS * PT * DF;
    perm_kernel<<<(pelems + 255) / 256, 256>>>(h);
    dim3 grid(SIZE / RPB, BS, NZ);               // 64 x 16 x 4
    alignment_kernel<<<grid, TPB>>>(sigma);
    const int celems = NROW * DF4;
    combine_kernel<<<(celems + 255) / 256, 256>>>((float*)d_out);
}

// round 12
// speedup vs baseline: 2.8775x; 1.4427x over previous
#include <cuda_runtime.h>
#include <cuda_bf16.h>
#include <math.h>

// Problem constants (fixed by setup_inputs)
#define BS    16
#define T     1024
#define DF    80          // feature dim
#define DF4   20          // as float4
#define SIZE  4096
#define TPB   256         // quad per row -> 64 rows per block
#define RPB   64
#define NZ    8           // split factor for WIDE groups
#define THRESH 96         // union width above which a group is split
#define GRPS  (SIZE / 8)  // 8-row groups per batch = 512
#define TPAD  8
#define PT    (T + TPAD)  // padded row count of h_perm
#define NROW  (BS * SIZE)
#define FULLM 0xFFFFFFFFu

// Device scratch (allocation-free)
__device__ float g_cs[BS * T];             // sorted centers
__device__ int   g_ci[BS * T];             // permutation
__device__ float g_hp[BS * PT * DF];       // h rows permuted by sorted order
__device__ int2  g_win[BS * GRPS];         // per 8-row group: union {wlo, whi}
__device__ float g_smax[NROW];             // per row: exact max score
__device__ float g_part[(size_t)NZ * NROW * DF];  // wide-row partial numerators
__device__ float g_lpart[NZ * NROW];              // wide-row partial denominators

// ---------------------------------------------------------------------------
// Kernel 1: fp32 cumsum replicating jax.lax.associative_scan's association
// tree, then centers, then bitonic sort by c (monotone for every batch,
// incl. batch 0 whose cumsum row is zeroed by the reference).
// ---------------------------------------------------------------------------
__global__ void prep_kernel(const float* __restrict__ d) {
    __shared__ float r[2047];
    __shared__ float s[2047];
    __shared__ float cv[T];
    __shared__ int   ci[T];
    const int b = blockIdx.x;
    const int t = threadIdx.x;

    const float v = d[b * T + t];
    r[t] = v;
    __syncthreads();

    {   // upsweep: pair sums
        int off = 0, n = T;
        while (n > 1) {
            int noff = off + n;
            if (t < (n >> 1))
                r[noff + t] = __fadd_rn(r[off + 2 * t], r[off + 2 * t + 1]);
            __syncthreads();
            off = noff; n >>= 1;
        }
    }
    if (t == 0) s[2046] = r[2046];
    __syncthreads();
    #pragma unroll
    for (int L = 9; L >= 0; --L) {   // downsweep
        const int n    = T >> L;
        const int off  = 2048 - (2048 >> L);
        const int offn = 2048 - (2048 >> (L + 1));
        if (t < n) {
            float val;
            if (t == 0)        val = r[off];
            else if (t & 1)    val = s[offn + (t >> 1)];
            else               val = __fadd_rn(s[offn + (t >> 1) - 1], r[off + t]);
            s[off + t] = val;
        }
        __syncthreads();
    }

    float cs;
    if (b == 0)       cs = 0.0f;         // reference zeroes whole batch-0 row
    else if (t == 0)  cs = s[T - 1];     // rolled: total sum
    else              cs = s[t - 1];     // exclusive prefix
    cv[t] = __fadd_rn(0.5f * v, cs);
    ci[t] = t;
    __syncthreads();

    for (int k = 2; k <= T; k <<= 1) {   // bitonic sort ascending by cv
        for (int j = k >> 1; j > 0; j >>= 1) {
            int i = t ^ j;
            if (i > t) {
                bool up = ((t & k) == 0);
                float a = cv[t], bb = cv[i];
                if ((a > bb) == up) {
                    cv[t] = bb; cv[i] = a;
                    int tmp = ci[t]; ci[t] = ci[i]; ci[i] = tmp;
                }
            }
            __syncthreads();
        }
    }
    g_cs[b * T + t] = cv[t];
    g_ci[b * T + t] = ci[t];
}

// ---------------------------------------------------------------------------
// Kernel 1b: h_perm[b][k][:] = h[b][ci[b][k]][:]; pad rows zeroed.
// ---------------------------------------------------------------------------
__global__ void perm_kernel(const float* __restrict__ h) {
    const int e = blockIdx.x * blockDim.x + threadIdx.x;
    const int c = e % DF;
    const int k = (e / DF) % PT;
    const int b = e / (DF * PT);
    if (b >= BS) return;
    float v = 0.0f;
    if (k < T) {
        int src = g_ci[b * T + k];
        v = h[((size_t)b * T + src) * DF + c];
    }
    g_hp[((size_t)b * PT + k) * DF + c] = v;
}

// ---------------------------------------------------------------------------
// Kernel 1c: per-row score_max + per-8-row-group union window table.
// One thread per row; quantization-faithful rounding as validated.
// ---------------------------------------------------------------------------
template<bool POW2>
__global__ void __launch_bounds__(256) win_kernel(const float* __restrict__ sigma) {
    __shared__ float c_sh[T];
    const int b = blockIdx.y;
    const int tid = threadIdx.x;
    const int s = blockIdx.x * 256 + tid;

    for (int i = tid; i < T; i += 256)
        c_sh[i] = g_cs[b * T + i];
    __syncthreads();

    const float sg     = sigma[0];
    const float two_s2 = 2.0f * sg * sg;
    const float inv2s2 = 1.0f / two_s2;
    const float tval   = (float)s + 1.5f;

    auto lower = [&](float x) -> int {
        int lo = 0, hi = T;
        while (lo < hi) {
            int m = (lo + hi) >> 1;
            if (c_sh[m] > x) hi = m; else lo = m + 1;
        }
        return lo;
    };

    int kc = lower(tval);
    int kA = kc < (T - 1) ? kc : (T - 1);
    int kB = (kc - 1) > 0 ? (kc - 1) : 0;
    float dA  = __fsub_rn(tval, c_sh[kA]);
    float dB  = __fsub_rn(tval, c_sh[kB]);
    float sqA = __fmul_rn(dA, dA);
    float sqB = __fmul_rn(dB, dB);
    float sqmin = fminf(sqA, sqB);
    const float score_max = POW2 ? -__fmul_rn(sqmin, inv2s2)
                                 : -__fdiv_rn(sqmin, two_s2);
    const float rr = sqrtf(sqmin + 24.0f * two_s2);
    int klo = lower(tval - rr);
    int khi = lower(tval + rr) - 1;

    g_smax[(size_t)b * SIZE + s] = score_max;

    // union over groups of 8 consecutive rows (lanes 8-aligned in warp)
    #pragma unroll
    for (int o = 1; o < 8; o <<= 1) {
        klo = min(klo, __shfl_xor_sync(FULLM, klo, o));
        khi = max(khi, __shfl_xor_sync(FULLM, khi, o));
    }
    if ((tid & 7) == 0)
        g_win[b * GRPS + (s >> 3)] = make_int2(klo, khi);
}

// ---------------------------------------------------------------------------
// Main kernel: quad per row, 8 rows per warp. NARROW groups (len<=THRESH):
// z=0 does the full window and writes out directly (R10 path). WIDE groups:
// all NZ z's each do one segment, writing partial slabs (R11 path).
// Quantization-faithful weights:
//   dt = fsub(t,c); sq = fmul(dt,dt); sc = -fdiv(sq,2s^2); e = fsub(sc,max)
// POW2: 2*sigma^2 power of two -> fmul by exact reciprocal == fdiv (bitwise).
// ---------------------------------------------------------------------------
template<bool POW2>
__global__ void __launch_bounds__(TPB) alignment_kernel(
    const float* __restrict__ sigma, float* __restrict__ out)
{
    __shared__ float c_sh[PT];
    __shared__ int   s_wide;
    const int b   = blockIdx.y;
    const int z   = blockIdx.z;
    const int bx  = blockIdx.x;
    const int tid = threadIdx.x;
    const int f   = tid & 3;
    const int row = tid >> 2;               // 0..63
    const int s   = bx * RPB + row;
    const int wrp = tid >> 5;               // warp id = row/8

    // block-level early exit: skip staging if all 8 groups are narrow (z>0)
    if (tid == 0) s_wide = 0;
    __syncthreads();
    if (tid < 8) {
        int2 wv = g_win[b * GRPS + bx * 8 + tid];
        if (wv.y - wv.x + 1 > THRESH) s_wide = 1;   // benign same-value race
    }
    __syncthreads();
    if (z > 0 && !s_wide) return;

    for (int i = tid; i < T; i += TPB)
        c_sh[i] = g_cs[b * T + i];
    if (tid < TPAD) c_sh[T + tid] = INFINITY;       // exp(-inf) = 0 padding
    __syncthreads();

    // this warp's group window
    int2 wv;
    if ((tid & 31) == 0) wv = g_win[b * GRPS + bx * 8 + wrp];
    wv.x = __shfl_sync(FULLM, wv.x, 0);
    wv.y = __shfl_sync(FULLM, wv.y, 0);
    const int wlo = wv.x, whi = wv.y;
    const int len = whi - wlo + 1;
    const bool narrow = (len <= THRESH);
    if (narrow && z > 0) return;

    const float sg     = sigma[0];
    const float two_s2 = 2.0f * sg * sg;
    const float inv2s2 = 1.0f / two_s2;
    const float tval   = (float)s + 1.5f;
    const float smax   = g_smax[(size_t)b * SIZE + s];

    const float4* __restrict__ hb =
        (const float4*)g_hp + (size_t)b * PT * DF4 + f;

    float  l = 0.0f;
    float4 acc[5];
    #pragma unroll
    for (int j = 0; j < 5; ++j) acc[j] = make_float4(0.f, 0.f, 0.f, 0.f);

    if (narrow) {
        // full window, no guard (overshoot terms are genuine; pad gives w=0)
        for (int k0 = wlo; k0 <= whi; k0 += 4) {
            float dt = __fsub_rn(tval, c_sh[k0 + f]);
            float sq = __fmul_rn(dt, dt);
            float sc = POW2 ? -__fmul_rn(sq, inv2s2) : -__fdiv_rn(sq, two_s2);
            float e  = __fsub_rn(sc, smax);
            float w0 = __expf(e);
            float w1 = __shfl_xor_sync(FULLM, w0, 1);
            float w2 = __shfl_xor_sync(FULLM, w0, 2);
            float w3 = __shfl_xor_sync(FULLM, w1, 2);
            l += ((w0 + w1) + (w2 + w3));
            const float4* p0 = hb + (size_t)(k0 + f)       * DF4;
            const float4* p1 = hb + (size_t)(k0 + (f ^ 1)) * DF4;
            const float4* p2 = hb + (size_t)(k0 + (f ^ 2)) * DF4;
            const float4* p3 = hb + (size_t)(k0 + (f ^ 3)) * DF4;
            #pragma unroll
            for (int j = 0; j < 5; ++j) {
                float4 v0 = p0[4 * j];
                acc[j].x += w0 * v0.x; acc[j].y += w0 * v0.y;
                acc[j].z += w0 * v0.z; acc[j].w += w0 * v0.w;
                float4 v1 = p1[4 * j];
                acc[j].x += w1 * v1.x; acc[j].y += w1 * v1.y;
                acc[j].z += w1 * v1.z; acc[j].w += w1 * v1.w;
                float4 v2 = p2[4 * j];
                acc[j].x += w2 * v2.x; acc[j].y += w2 * v2.y;
                acc[j].z += w2 * v2.z; acc[j].w += w2 * v2.w;
                float4 v3 = p3[4 * j];
                acc[j].x += w3 * v3.x; acc[j].y += w3 * v3.y;
                acc[j].z += w3 * v3.z; acc[j].w += w3 * v3.w;
            }
        }
        // warp-local denominator is per-row already (each lane summed its
        // quad's 4 k's... NO: l here is the full-window sum per lane group).
        // l as computed: each lane accumulated w0+w1+w2+w3 = sum over ALL 4
        // k's of each chunk -> every lane holds the full window sum. Good.
        const float linv = 1.0f / l;
        float4* o = (float4*)out + ((size_t)b * SIZE + s) * DF4 + f;
        #pragma unroll
        for (int j = 0; j < 5; ++j) {
            float4 v;
            v.x = acc[j].x * linv; v.y = acc[j].y * linv;
            v.z = acc[j].z * linv; v.w = acc[j].w * linv;
            o[4 * j] = v;
        }
    } else {
        // z-th segment of the union window, guard against double-counting
        const int zlo = wlo + (len * z) / NZ;
        const int zhi = wlo + (len * (z + 1)) / NZ - 1;
        for (int k0 = zlo; k0 <= zhi; k0 += 4) {
            const int kk = k0 + f;
            float dt = __fsub_rn(tval, c_sh[kk]);
            float sq = __fmul_rn(dt, dt);
            float sc = POW2 ? -__fmul_rn(sq, inv2s2) : -__fdiv_rn(sq, two_s2);
            float e  = __fsub_rn(sc, smax);
            float w0 = __expf(e);
            if (kk > zhi) w0 = 0.0f;
            float w1 = __shfl_xor_sync(FULLM, w0, 1);
            float w2 = __shfl_xor_sync(FULLM, w0, 2);
            float w3 = __shfl_xor_sync(FULLM, w1, 2);
            l += ((w0 + w1) + (w2 + w3));
            const float4* p0 = hb + (size_t)(k0 + f)       * DF4;
            const float4* p1 = hb + (size_t)(k0 + (f ^ 1)) * DF4;
            const float4* p2 = hb + (size_t)(k0 + (f ^ 2)) * DF4;
            const float4* p3 = hb + (size_t)(k0 + (f ^ 3)) * DF4;
            #pragma unroll
            for (int j = 0; j < 5; ++j) {
                float4 v0 = p0[4 * j];
                acc[j].x += w0 * v0.x; acc[j].y += w0 * v0.y;
                acc[j].z += w0 * v0.z; acc[j].w += w0 * v0.w;
                float4 v1 = p1[4 * j];
                acc[j].x += w1 * v1.x; acc[j].y += w1 * v1.y;
                acc[j].z += w1 * v1.z; acc[j].w += w1 * v1.w;
                float4 v2 = p2[4 * j];
                acc[j].x += w2 * v2.x; acc[j].y += w2 * v2.y;
                acc[j].z += w2 * v2.z; acc[j].w += w2 * v2.w;
                float4 v3 = p3[4 * j];
                acc[j].x += w3 * v3.x; acc[j].y += w3 * v3.y;
                acc[j].z += w3 * v3.z; acc[j].w += w3 * v3.w;
            }
        }
        const size_t rowid = (size_t)b * SIZE + s;
        float4* po = (float4*)g_part + ((size_t)z * NROW + rowid) * DF4 + f;
        #pragma unroll
        for (int j = 0; j < 5; ++j) po[4 * j] = acc[j];
        if (f == 0) g_lpart[(size_t)z * NROW + rowid] = l;
    }
}

// ---------------------------------------------------------------------------
// Kernel 3: combine — only for WIDE rows (narrow rows already written).
// ---------------------------------------------------------------------------
__global__ void combine_kernel(float* __restrict__ out) {
    const int e = blockIdx.x * blockDim.x + threadIdx.x;  // float4 id
    if (e >= NROW * DF4) return;
    const int rowid = e / DF4;
    const int b = rowid / SIZE;
    const int s = rowid % SIZE;

    int2 wv = g_win[b * GRPS + (s >> 3)];
    if (wv.y - wv.x + 1 <= THRESH) return;   // narrow: main wrote out already

    float lsum = 0.0f;
    #pragma unroll
    for (int z = 0; z < NZ; ++z)
        lsum += g_lpart[(size_t)z * NROW + rowid];

    float4 v = make_float4(0.f, 0.f, 0.f, 0.f);
    #pragma unroll
    for (int z = 0; z < NZ; ++z) {
        float4 p = ((const float4*)g_part)[(size_t)z * NROW * DF4 + e];
        v.x += p.x; v.y += p.y; v.z += p.z; v.w += p.w;
    }
    const float linv = 1.0f / lsum;
    v.x *= linv; v.y *= linv; v.z *= linv; v.w *= linv;
    ((float4*)out)[e] = v;
}

// ---------------------------------------------------------------------------
extern "C" void kernel_launch(void* const* d_in, const int* in_sizes, int n_in,
                              void* d_out, int out_size) {
    const float* h     = (const float*)d_in[0];  // [16,1024,80]
    const float* d     = (const float*)d_in[1];  // [16,1024]
    const float* sigma = (const float*)d_in[2];  // [1]

    prep_kernel<<<BS, T>>>(d);
    const int pelems = BS * PT * DF;
    perm_kernel<<<(pelems + 255) / 256, 256>>>(h);

    dim3 wgrid(SIZE / 256, BS);
    dim3 mgrid(SIZE / RPB, BS, NZ);              // 64 x 16 x 8
    // POW2 dispatch must be identical in win/main: both derive it the same
    // way on-device is impossible for templates, so dispatch on host is not
    // allowed (sigma is device memory). Launch both templates? No — derive
    // per-kernel on device is required. Instead: win/main take a runtime
    // flag... simplest correct: use the non-template dispatch inside each
    // kernel. Here both kernels are templated; launch the POW2=true pair and
    // guard inside? NO — we cannot read sigma on host.
    // Resolution: launch a template selector via a tiny device-side check is
    // impossible; so both win_kernel and alignment_kernel internally recompute
    // pow2 and the templates are instantiated with a dummy; to keep this
    // robust we launch the generic (POW2=false) versions ONLY — correctness
    // is identical (fdiv path is the reference-faithful one; POW2 was purely
    // a speed tweak inside the loop).
    win_kernel<false><<<wgrid, 256>>>(sigma);
    alignment_kernel<false><<<mgrid, TPB>>>(sigma, (float*)d_out);
    const int celems = NROW * DF4;
    combine_kernel<<<(celems + 255) / 256, 256>>>((float*)d_out);
}

// round 13
// speedup vs baseline: 3.1544x; 1.0962x over previous
#include <cuda_runtime.h>
#include <math.h>

// Problem constants (fixed by setup_inputs)
#define BS    16
#define T     1024
#define DF    80
#define DF4   20
#define SIZE  4096
#define TPB   128         // quad per row -> 32 rows per block
#define RPB   32
#define GPB   4           // 8-row groups per block
#define NZ    16          // split factor for WIDE groups
#define THRESH 96
#define GRPS  (SIZE / 8)  // 512
#define TPAD  8
#define PT    (T + TPAD)
#define NROW  (BS * SIZE)
#define KMAX  150         // h-tile rows staged in smem (150*320B = 48000B)
#define FULLM 0xFFFFFFFFu

// Device scratch (allocation-free)
__device__ float g_cs[BS * PT];            // sorted centers (+INF pad)
__device__ int   g_ci[BS * PT];            // permutation   (0 pad)
__device__ float g_hp[BS * PT * DF];       // h rows permuted (0 pad)
__device__ int2  g_win[BS * GRPS];         // per 8-row group: union {wlo,whi}
__device__ float g_smax[NROW];             // per row: exact max score
__device__ float g_part[(size_t)NZ * NROW * DF];  // wide partial numerators
__device__ float g_lpart[NZ * NROW];              // wide partial denominators

// ---------------------------------------------------------------------------
// Kernel 1: prep.
// b==0: reference zeroes the cumsum row -> c = d/2 exactly; needs a SORT.
//       Hybrid bitonic: smem steps only for j>=32 (30 barriers), shfl below.
// b>0 : c = d/2 + exclusive-prefix (assoc-scan tree, fp32, reference-faithful)
//       is ALREADY ascending for t=1..1023 (fp adds of nonneg are monotone),
//       and c[0] = total + d/2 is the max -> sorted order is a ROTATION.
// ---------------------------------------------------------------------------
__global__ void prep_kernel(const float* __restrict__ d) {
    __shared__ float r[2047];
    __shared__ float sarr[2047];
    __shared__ float sv[T];
    __shared__ int   si[T];
    const int b = blockIdx.x;
    const int t = threadIdx.x;
    const float v = d[b * T + t];

    if (b == 0) {
        float key = 0.5f * v;     // == fadd(0.5*v, 0): exact
        int   idx = t;
        for (int k = 2; k <= T; k <<= 1) {
            for (int j = k >> 1; j >= 32; j >>= 1) {     // cross-warp: smem
                sv[t] = key; si[t] = idx;
                __syncthreads();
                int p = t ^ j;
                float pv = sv[p]; int pi = si[p];
                bool keepmin = (((t & k) == 0) == ((t & j) == 0));
                bool take = keepmin ? (pv < key) : (pv > key);
                if (take) { key = pv; idx = pi; }
                __syncthreads();
            }
            const int j0 = (k >> 1) < 16 ? (k >> 1) : 16;
            for (int j = j0; j >= 1; j >>= 1) {          // in-warp: shfl
                float pv = __shfl_xor_sync(FULLM, key, j);
                int   pi = __shfl_xor_sync(FULLM, idx, j);
                bool keepmin = (((t & k) == 0) == ((t & j) == 0));
                bool take = keepmin ? (pv < key) : (pv > key);
                if (take) { key = pv; idx = pi; }
            }
        }
        g_cs[t] = key;
        g_ci[t] = idx;
    } else {
        // fp32 tree scan replicating jax.lax.associative_scan
        r[t] = v;
        __syncthreads();
        {   // upsweep
            int off = 0, n = T;
            while (n > 1) {
                int noff = off + n;
                if (t < (n >> 1))
                    r[noff + t] = __fadd_rn(r[off + 2 * t], r[off + 2 * t + 1]);
                __syncthreads();
                off = noff; n >>= 1;
            }
        }
        if (t == 0) sarr[2046] = r[2046];
        __syncthreads();
        #pragma unroll
        for (int L = 9; L >= 0; --L) {   // downsweep
            const int n    = T >> L;
            const int off  = 2048 - (2048 >> L);
            const int offn = 2048 - (2048 >> (L + 1));
            if (t < n) {
                float val;
                if (t == 0)     val = r[off];
                else if (t & 1) val = sarr[offn + (t >> 1)];
                else            val = __fadd_rn(sarr[offn + (t >> 1) - 1], r[off + t]);
                sarr[off + t] = val;
            }
            __syncthreads();
        }
        float cs = (t == 0) ? sarr[T - 1] : sarr[t - 1];   // roll
        float cv = __fadd_rn(0.5f * v, cs);
        // sorted = rotation: ascending is cv[1..1023], then cv[0]
        int dest = (t == 0) ? (T - 1) : (t - 1);
        g_cs[b * PT + dest] = cv;
        g_ci[b * PT + dest] = t;
    }
    if (t < TPAD) { g_cs[b * PT + T + t] = INFINITY; g_ci[b * PT + T + t] = 0; }
}

// ---------------------------------------------------------------------------
// Kernel 1b: h_perm[b][k][:] = h[b][ci[b][k]][:]; pad rows zeroed.
// ---------------------------------------------------------------------------
__global__ void perm_kernel(const float* __restrict__ h) {
    const int e = blockIdx.x * blockDim.x + threadIdx.x;
    const int c = e % DF;
    const int k = (e / DF) % PT;
    const int b = e / (DF * PT);
    if (b >= BS) return;
    float v = 0.0f;
    if (k < T) {
        int src = g_ci[b * PT + k];
        v = h[((size_t)b * T + src) * DF + c];
    }
    g_hp[((size_t)b * PT + k) * DF + c] = v;
}

// ---------------------------------------------------------------------------
// Kernel 1c: per-row score_max + per-8-row-group union window table.
// Quantization-faithful rounding (fdiv; == fmul-by-recip when 2s^2 is pow2).
// ---------------------------------------------------------------------------
__global__ void __launch_bounds__(256) win_kernel(const float* __restrict__ sigma) {
    __shared__ float c_sh[T];
    const int b = blockIdx.y;
    const int tid = threadIdx.x;
    const int s = blockIdx.x * 256 + tid;

    for (int i = tid; i < T; i += 256)
        c_sh[i] = g_cs[b * PT + i];
    __syncthreads();

    const float sg     = sigma[0];
    const float two_s2 = 2.0f * sg * sg;
    const float tval   = (float)s + 1.5f;

    auto lower = [&](float x) -> int {
        int lo = 0, hi = T;
        while (lo < hi) {
            int m = (lo + hi) >> 1;
            if (c_sh[m] > x) hi = m; else lo = m + 1;
        }
        return lo;
    };

    int kc = lower(tval);
    int kA = kc < (T - 1) ? kc : (T - 1);
    int kB = (kc - 1) > 0 ? (kc - 1) : 0;
    float dA  = __fsub_rn(tval, c_sh[kA]);
    float dB  = __fsub_rn(tval, c_sh[kB]);
    float sqA = __fmul_rn(dA, dA);
    float sqB = __fmul_rn(dB, dB);
    float sqmin = fminf(sqA, sqB);
    const float score_max = -__fdiv_rn(sqmin, two_s2);
    const float rr = sqrtf(sqmin + 24.0f * two_s2);
    int klo = lower(tval - rr);
    int khi = lower(tval + rr) - 1;

    g_smax[(size_t)b * SIZE + s] = score_max;

    #pragma unroll
    for (int o = 1; o < 8; o <<= 1) {        // union over 8 consecutive rows
        klo = min(klo, __shfl_xor_sync(FULLM, klo, o));
        khi = max(khi, __shfl_xor_sync(FULLM, khi, o));
    }
    if ((tid & 7) == 0)
        g_win[b * GRPS + (s >> 3)] = make_int2(klo, khi);
}

// ---------------------------------------------------------------------------
// Inner body: chunk-of-4 quad loop; h from smem tile (USM) or global.
// Weights quantization-faithful:
//   dt=fsub; sq=fmul; sc=-fdiv(sq,2s^2) [POW2: fmul by exact recip == fdiv];
//   e=fsub(sc,smax); w=expf(e). Guard kk>ahi gives exact segment partition.
// ---------------------------------------------------------------------------
template<bool POW2, bool USM>
__device__ __forceinline__ float body(
    const float* __restrict__ cb,            // g_cs + b*PT
    const float4* __restrict__ hpb,          // global h_perm batch base
    float4 (&hsm)[KMAX * DF4], int kbase,
    int alo, int ahi, int f, float tval, float smax,
    float two_s2, float inv2s2, float4* acc)
{
    float l = 0.0f;
    for (int k0 = alo; k0 <= ahi; k0 += 4) {
        const int kk = k0 + f;
        float cc = __ldg(cb + kk);
        float dt = __fsub_rn(tval, cc);
        float sq = __fmul_rn(dt, dt);
        float sc = POW2 ? -__fmul_rn(sq, inv2s2) : -__fdiv_rn(sq, two_s2);
        float e  = __fsub_rn(sc, smax);
        float w0 = __expf(e);
        if (kk > ahi) w0 = 0.0f;
        float w1 = __shfl_xor_sync(FULLM, w0, 1);
        float w2 = __shfl_xor_sync(FULLM, w0, 2);
        float w3 = __shfl_xor_sync(FULLM, w1, 2);
        l += ((w0 + w1) + (w2 + w3));

        const int r0 = k0 + f, r1 = k0 + (f ^ 1), r2 = k0 + (f ^ 2), r3 = k0 + (f ^ 3);
        #pragma unroll
        for (int j = 0; j < 5; ++j) {
            const int col = f + 4 * j;
            float4 v0 = USM ? hsm[(r0 - kbase) * DF4 + col] : hpb[(size_t)r0 * DF4 + col];
            acc[j].x += w0 * v0.x; acc[j].y += w0 * v0.y;
            acc[j].z += w0 * v0.z; acc[j].w += w0 * v0.w;
            float4 v1 = USM ? hsm[(r1 - kbase) * DF4 + col] : hpb[(size_t)r1 * DF4 + col];
            acc[j].x += w1 * v1.x; acc[j].y += w1 * v1.y;
            acc[j].z += w1 * v1.z; acc[j].w += w1 * v1.w;
            float4 v2 = USM ? hsm[(r2 - kbase) * DF4 + col] : hpb[(size_t)r2 * DF4 + col];
            acc[j].x += w2 * v2.x; acc[j].y += w2 * v2.y;
            acc[j].z += w2 * v2.z; acc[j].w += w2 * v2.w;
            float4 v3 = USM ? hsm[(r3 - kbase) * DF4 + col] : hpb[(size_t)r3 * DF4 + col];
            acc[j].x += w3 * v3.x; acc[j].y += w3 * v3.y;
            acc[j].z += w3 * v3.z; acc[j].w += w3 * v3.w;
        }
    }
    return l;
}

// ---------------------------------------------------------------------------
// Main kernel: 32 rows/block. Narrow groups: z==0 full window -> direct out.
// Wide groups: all NZ z's do one segment each -> slabs. The block stages its
// union k-range of h_perm into a 48KB smem tile when it fits (KMAX rows).
// ---------------------------------------------------------------------------
__global__ void __launch_bounds__(TPB) alignment_kernel(
    const float* __restrict__ sigma, float* __restrict__ out)
{
    __shared__ float4 h_sm[KMAX * DF4];      // 48000 B
    __shared__ int s_klo, s_khi;
    const int b   = blockIdx.y;
    const int z   = blockIdx.z;
    const int bx  = blockIdx.x;
    const int tid = threadIdx.x;
    const int f   = tid & 3;
    const int row = tid >> 2;                // 0..31
    const int s   = bx * RPB + row;
    const int wrp = tid >> 5;                // 0..3

    const int2 wv = g_win[b * GRPS + bx * GPB + wrp];
    const int wlo = wv.x, whi = wv.y, len = whi - wlo + 1;
    const bool narrow = (len <= THRESH);
    bool active;
    int alo, ahi;
    if (narrow) { active = (z == 0); alo = wlo; ahi = whi; }
    else        { active = true;
                  alo = wlo + (len * z) / NZ;
                  ahi = wlo + (len * (z + 1)) / NZ - 1; }

    if (tid == 0) { s_klo = 0x7FFFFFFF; s_khi = -1; }
    __syncthreads();
    if (active && (tid & 31) == 0) { atomicMin(&s_klo, alo); atomicMax(&s_khi, ahi); }
    __syncthreads();
    if (s_khi < 0) return;                   // whole block inactive (uniform)

    const int kbase  = s_klo;
    const int kcount = s_khi + 4 - kbase;    // loop reads rows up to ahi+3
    const bool usm   = (kcount <= KMAX);
    const float4* __restrict__ hpb = (const float4*)g_hp + (size_t)b * PT * DF4;

    if (usm) {
        const float4* src = hpb + (size_t)kbase * DF4;
        for (int i = tid; i < kcount * DF4; i += TPB) h_sm[i] = src[i];
    }
    __syncthreads();
    if (!active) return;                     // after all block-wide syncs

    const float sg     = sigma[0];
    const float two_s2 = 2.0f * sg * sg;
    const unsigned tb  = __float_as_uint(two_s2);
    const bool pow2    = ((tb & 0x007FFFFFu) == 0u) && (two_s2 > 0.0f);
    const float inv2s2 = 1.0f / two_s2;      // exact reciprocal when pow2
    const float tval   = (float)s + 1.5f;
    const float smax   = g_smax[(size_t)b * SIZE + s];
    const float* cb    = g_cs + b * PT;

    float4 acc[5];
    #pragma unroll
    for (int j = 0; j < 5; ++j) acc[j] = make_float4(0.f, 0.f, 0.f, 0.f);

    float l;
    if (pow2) {
        if (usm) l = body<true , true >(cb, hpb, h_sm, kbase, alo, ahi, f, tval, smax, two_s2, inv2s2, acc);
        else     l = body<true , false>(cb, hpb, h_sm, kbase, alo, ahi, f, tval, smax, two_s2, inv2s2, acc);
    } else {
        if (usm) l = body<false, true >(cb, hpb, h_sm, kbase, alo, ahi, f, tval, smax, two_s2, inv2s2, acc);
        else     l = body<false, false>(cb, hpb, h_sm, kbase, alo, ahi, f, tval, smax, two_s2, inv2s2, acc);
    }

    if (narrow) {
        const float linv = 1.0f / l;
        float4* o = (float4*)out + ((size_t)b * SIZE + s) * DF4 + f;
        #pragma unroll
        for (int j = 0; j < 5; ++j) {
            float4 v;
            v.x = acc[j].x * linv; v.y = acc[j].y * linv;
            v.z = acc[j].z * linv; v.w = acc[j].w * linv;
            o[4 * j] = v;
        }
    } else {
        const size_t rowid = (size_t)b * SIZE + s;
        float4* po = (float4*)g_part + ((size_t)z * NROW + rowid) * DF4 + f;
        #pragma unroll
        for (int j = 0; j < 5; ++j) po[4 * j] = acc[j];
        if (f == 0) g_lpart[(size_t)z * NROW + rowid] = l;
    }
}

// ---------------------------------------------------------------------------
// Kernel 3: combine — only WIDE rows (narrow written directly by main).
// ---------------------------------------------------------------------------
__global__ void combine_kernel(float* __restrict__ out) {
    const int e = blockIdx.x * blockDim.x + threadIdx.x;  // float4 id
    if (e >= NROW * DF4) return;
    const int rowid = e / DF4;
    const int b = rowid / SIZE;
    const int s = rowid % SIZE;

    int2 wv = g_win[b * GRPS + (s >> 3)];
    if (wv.y - wv.x + 1 <= THRESH) return;

    float lsum = 0.0f;
    #pragma unroll
    for (int z = 0; z < NZ; ++z)
        lsum += g_lpart[(size_t)z * NROW + rowid];

    float4 v = make_float4(0.f, 0.f, 0.f, 0.f);
    #pragma unroll
    for (int z = 0; z < NZ; ++z) {
        float4 p = ((const float4*)g_part)[(size_t)z * NROW * DF4 + e];
        v.x += p.x; v.y += p.y; v.z += p.z; v.w += p.w;
    }
    const float linv = 1.0f / lsum;
    v.x *= linv; v.y *= linv; v.z *= linv; v.w *= linv;
    ((float4*)out)[e] = v;
}

// ---------------------------------------------------------------------------
extern "C" void kernel_launch(void* const* d_in, const int* in_sizes, int n_in,
                              void* d_out, int out_size) {
    const float* h     = (const float*)d_in[0];  // [16,1024,80]
    const float* d     = (const float*)d_in[1];  // [16,1024]
    const float* sigma = (const float*)d_in[2];  // [1]

    prep_kernel<<<BS, T>>>(d);
    const int pelems = BS * PT * DF;
    perm_kernel<<<(pelems + 255) / 256, 256>>>(h);

    dim3 wgrid(SIZE / 256, BS);
    win_kernel<<<wgrid, 256>>>(sigma);

    dim3 mgrid(SIZE / RPB, BS, NZ);              // 128 x 16 x 16
    alignment_kernel<<<mgrid, TPB>>>(sigma, (float*)d_out);

    const int celems = NROW * DF4;
    combine_kernel<<<(celems + 255) / 256, 256>>>((float*)d_out);
}